// round 11
// baseline (speedup 1.0000x reference)
#include <cuda_runtime.h>
#include <math.h>

static constexpr int B  = 2;
static constexpr int S  = 2048;
static constexpr int D  = 1024;
static constexpr int H  = 8;
static constexpr int DHD = 128;
static constexpr int RD = 256;
static constexpr int FD = 4096;
static constexpr int M  = B * S;     // 4096
static constexpr int BH = B * H;     // 16
static constexpr int SCH = 128;      // scan chunk length
static constexpr int NCH = S / SCH;  // 16

// ---------------- scratch (static device globals; no allocations) ----------------
__device__ float g_xn[M * D];
__device__ float g_q[M * D];
__device__ float g_k[M * D];       // becomes k_scaled in place
__device__ float g_v[M * D];
__device__ float g_z[M * D];
__device__ float g_dbuf[M * RD];
__device__ float g_gamma[M * D];
__device__ float g_lga[M * D];
__device__ float g_csum[B * NCH * D];
__device__ float g_cpref[B * NCH * D];
__device__ float g_h[M * D];       // h_seq [B][S][D]
__device__ float g_ctx[M * D];
__device__ float g_y[M * D];
__device__ float g_yn[M * D];
__device__ float g_f1[M * FD];
__device__ float g_scores[(size_t)BH * S * S];   // 268 MB, softmax in place

// One flag per 128B L2 line.
static constexpr int FPAD = 32;
__device__ int g_flag[128 * FPAD];

__device__ __forceinline__ void st_rel_gpu(int* p, int v) {
    asm volatile("st.release.gpu.global.b32 [%0], %1;" :: "l"(p), "r"(v) : "memory");
}

// ---------------- rmsnorm ----------------
__global__ void rmsnorm_kernel(const float* __restrict__ x, const float* __restrict__ w,
                               float* __restrict__ out) {
    int row = blockIdx.x;
    const float* xr = x + (size_t)row * D;
    float ss = 0.f;
    for (int i = threadIdx.x; i < D; i += 256) { float v = xr[i]; ss += v * v; }
#pragma unroll
    for (int o = 16; o; o >>= 1) ss += __shfl_xor_sync(0xffffffffu, ss, o);
    __shared__ float wsum[8];
    int wid = threadIdx.x >> 5, lane = threadIdx.x & 31;
    if (lane == 0) wsum[wid] = ss;
    __syncthreads();
    if (threadIdx.x == 0) {
        float t = 0.f;
        for (int i = 0; i < 8; i++) t += wsum[i];
        wsum[0] = t;
    }
    __syncthreads();
    float inv = 1.f / (sqrtf(wsum[0] / (float)D) + 1e-6f);
    for (int i = threadIdx.x; i < D; i += 256)
        out[(size_t)row * D + i] = w[i] * xr[i] * inv;
}

// ---------------- SGEMM v3: BK=16 double-buffered (half the syncs of BK=8) ----
// C = act(A@W + bias) (+ residual). 128x128 tile, 256 threads, 8x8/thread.
// K must be a multiple of 16 (1024/256/4096 all are).
template <int EPI, int RES>
__global__ void __launch_bounds__(256, 2) sgemm_kernel(
    const float* __restrict__ A, const float* __restrict__ W,
    const float* __restrict__ bias, const float* __restrict__ Rp,
    float* __restrict__ C, int N, int K) {
    __shared__ __align__(16) float As[2][16][128];
    __shared__ __align__(16) float Ws[2][16][128];
    int bn = blockIdx.x * 128, bm = blockIdx.y * 128;
    int tid = threadIdx.x;
    int tx = tid & 15, ty = tid >> 4;
    int rowA = tid >> 1, colA = (tid & 1) * 8;   // A: 128 rows x 16 k, 8 k-elems/thread
    int rowW = tid >> 4, colW = (tid & 15) * 8;  // W: 16 k-rows x 128 cols, 8 cols/thread
    float acc[8][8] = {};
    const float* Aptr = A + (size_t)(bm + rowA) * K + colA;
    const float* Wptr = W + (size_t)rowW * N + bn + colW;

    // prologue: k0 = 0 into buffer 0
    {
        float4 a0 = *(const float4*)(Aptr);
        float4 a1 = *(const float4*)(Aptr + 4);
        float4 w0 = *(const float4*)(Wptr);
        float4 w1 = *(const float4*)(Wptr + 4);
        As[0][colA + 0][rowA] = a0.x; As[0][colA + 1][rowA] = a0.y;
        As[0][colA + 2][rowA] = a0.z; As[0][colA + 3][rowA] = a0.w;
        As[0][colA + 4][rowA] = a1.x; As[0][colA + 5][rowA] = a1.y;
        As[0][colA + 6][rowA] = a1.z; As[0][colA + 7][rowA] = a1.w;
        *(float4*)&Ws[0][rowW][colW]     = w0;
        *(float4*)&Ws[0][rowW][colW + 4] = w1;
    }
    __syncthreads();

    int buf = 0;
    for (int k0 = 0; k0 < K; k0 += 16) {
        bool more = (k0 + 16) < K;
        float4 a0, a1, w0, w1;
        if (more) {
            a0 = *(const float4*)(Aptr + k0 + 16);
            a1 = *(const float4*)(Aptr + k0 + 20);
            w0 = *(const float4*)(Wptr + (size_t)(k0 + 16) * N);
            w1 = *(const float4*)(Wptr + (size_t)(k0 + 16) * N + 4);
        }
#pragma unroll
        for (int kk = 0; kk < 16; kk++) {
            float a[8], bv[8];
            *(float4*)&a[0]  = *(const float4*)&As[buf][kk][ty * 8];
            *(float4*)&a[4]  = *(const float4*)&As[buf][kk][ty * 8 + 4];
            *(float4*)&bv[0] = *(const float4*)&Ws[buf][kk][tx * 8];
            *(float4*)&bv[4] = *(const float4*)&Ws[buf][kk][tx * 8 + 4];
#pragma unroll
            for (int i = 0; i < 8; i++)
#pragma unroll
                for (int j = 0; j < 8; j++)
                    acc[i][j] = fmaf(a[i], bv[j], acc[i][j]);
        }
        if (more) {
            int nb = buf ^ 1;
            As[nb][colA + 0][rowA] = a0.x; As[nb][colA + 1][rowA] = a0.y;
            As[nb][colA + 2][rowA] = a0.z; As[nb][colA + 3][rowA] = a0.w;
            As[nb][colA + 4][rowA] = a1.x; As[nb][colA + 5][rowA] = a1.y;
            As[nb][colA + 6][rowA] = a1.z; As[nb][colA + 7][rowA] = a1.w;
            *(float4*)&Ws[nb][rowW][colW]     = w0;
            *(float4*)&Ws[nb][rowW][colW + 4] = w1;
        }
        __syncthreads();
        buf ^= 1;
    }

    int r0 = bm + ty * 8, c0 = bn + tx * 8;
#pragma unroll
    for (int i = 0; i < 8; i++) {
        size_t ro = (size_t)(r0 + i) * N;
#pragma unroll
        for (int j = 0; j < 8; j++) {
            float val = acc[i][j] + bias[c0 + j];
            if (EPI == 1) val = fmaxf(val, 0.f);
            if (EPI == 2) {
                val = 1.f / (1.f + expf(-val));
                val = fminf(fmaxf(val, 1e-6f), 1.f - 1e-6f);
            }
            if (EPI == 3) {
                float u = val;
                float t = tanhf(0.7978845608028654f * (u + 0.044715f * u * u * u));
                val = 0.5f * u * (1.f + t);
            }
            if (RES) val += Rp[ro + c0 + j];
            C[ro + c0 + j] = val;
        }
    }
}

// ---------------- scan ----------------
__global__ void scan_chunk_kernel() {
    int d = blockIdx.x * 128 + threadIdx.x;
    int ch = blockIdx.y, b = blockIdx.z;
    size_t base = ((size_t)b * S + (size_t)ch * SCH) * D + d;
    float acc = 0.f;
    for (int s = 0; s < SCH; s++) {
        size_t idx = base + (size_t)s * D;
        acc += logf(g_gamma[idx]);
        g_lga[idx] = acc;
    }
    g_csum[((size_t)b * NCH + ch) * D + d] = acc;
}

__global__ void scan_pref_kernel() {
    int d = blockIdx.x * 128 + threadIdx.x;
    int b = blockIdx.y;
    float run = 0.f;
    for (int c = 0; c < NCH; c++) {
        size_t idx = ((size_t)b * NCH + c) * D + d;
        g_cpref[idx] = run;
        run += g_csum[idx];
    }
}

__global__ void kscale_kernel() {
    const int n = M * D;
    for (int idx = blockIdx.x * 256 + threadIdx.x; idx < n; idx += gridDim.x * 256) {
        int b = idx >> 21;
        int s = (idx >> 10) & (S - 1);
        int d = idx & (D - 1);
        int ch = s >> 7;
        float pref = g_cpref[((size_t)b * NCH + ch) * D + d];
        g_k[idx] = g_k[idx] * expf(g_lga[idx] + pref);
    }
}

// ---------------- sequential recurrence v5: 32 blocks x 1024 threads ----------------
// Straggler tail and poll fan-in scale with barrier participants: 128 -> 32.
// Per-thread dot work unchanged (warp per column, 32 cols/block).
// Dynamic smem: Wgs 128KB + hs 8KB + res 256B.
static constexpr int RBLK = 32;                 // blocks
static constexpr int RCOL = 32;                 // columns per block
static constexpr size_t RECUR_SMEM = (size_t)(RCOL * D + 2 * D + 64) * 4;

__global__ void flag_reset_kernel() {
    for (int i = blockIdx.x * 256 + threadIdx.x; i < 128 * FPAD; i += gridDim.x * 256)
        g_flag[i] = 0;
}

__global__ void __launch_bounds__(1024, 1) recur_kernel(const float* __restrict__ Wg,
                                                        const float* __restrict__ bg) {
    extern __shared__ __align__(16) float smem[];
    float* Wgs = smem;                // [RCOL * D] column-contiguous
    float* hs  = smem + RCOL * D;     // [2 * D]
    float* res = hs + 2 * D;          // [64]
    int tid = threadIdx.x;
    int j0 = blockIdx.x * RCOL;
    for (int idx = tid; idx < RCOL * D; idx += 1024) {
        int i = idx >> 5, c = idx & 31;
        Wgs[c * D + i] = Wg[(size_t)i * D + j0 + c];
    }
    __syncthreads();
    int w = tid >> 5, lane = tid & 31;   // warp w handles column j0 + w
    int j = j0 + w;
    float bgj = bg[j];
    const float* Wcol = &Wgs[w * D];
    volatile int* flags = g_flag;

    // prefetch z/gamma for s = 0
    float zv = 0.f, gv = 0.f;
    if (lane < 2) {
        size_t off0 = (size_t)lane * S * D + j;
        zv = g_z[off0];
        gv = g_gamma[off0];
    }

    for (int s = 0; s < S; s++) {
        float d0 = 0.f, d1 = 0.f;
        if (s > 0) {
            // stage h_{s-1} (both batches) into smem: 512 float4 over first 512 threads
            if (tid < 512) {
                int bsel = tid >> 8;
                int i4 = (tid & 255) * 4;
                *(float4*)&hs[bsel * D + i4] =
                    *(const float4*)&g_h[((size_t)(bsel ? S : 0) + s - 1) * D + i4];
            }
            __syncthreads();
#pragma unroll
            for (int r = 0; r < 8; r++) {
                int i4 = (r * 32 + lane) * 4;
                float4 wv = *(const float4*)&Wcol[i4];
                float4 h0 = *(const float4*)&hs[i4];
                float4 h1 = *(const float4*)&hs[D + i4];
                d0 = fmaf(h0.x, wv.x, d0); d1 = fmaf(h1.x, wv.x, d1);
                d0 = fmaf(h0.y, wv.y, d0); d1 = fmaf(h1.y, wv.y, d1);
                d0 = fmaf(h0.z, wv.z, d0); d1 = fmaf(h1.z, wv.z, d1);
                d0 = fmaf(h0.w, wv.w, d0); d1 = fmaf(h1.w, wv.w, d1);
            }
#pragma unroll
            for (int o = 16; o; o >>= 1) {
                d0 += __shfl_xor_sync(0xffffffffu, d0, o);
                d1 += __shfl_xor_sync(0xffffffffu, d1, o);
            }
        }
        if (lane < 2) {
            float dotv = lane ? d1 : d0;
            float hp = (s > 0) ? hs[lane * D + j] : 0.f;
            float sg = 1.f / (1.f + expf(-(dotv + bgj)));
            res[lane * RCOL + w] = zv * sg + gv * hp;
        }
        __syncthreads();
        // prefetch z/gamma for s+1 (hides behind poll)
        if (s + 1 < S && lane < 2) {
            size_t offn = ((size_t)lane * S + s + 1) * D + j;
            zv = g_z[offn];
            gv = g_gamma[offn];
        }
        // tid0: coalesced h store (8x STG.128) + release flag
        if (tid == 0) {
            float4 r0 = *(float4*)&res[0];
            float4 r1 = *(float4*)&res[4];
            float4 r2 = *(float4*)&res[8];
            float4 r3 = *(float4*)&res[12];
            float4 r4 = *(float4*)&res[16];
            float4 r5 = *(float4*)&res[20];
            float4 r6 = *(float4*)&res[24];
            float4 r7 = *(float4*)&res[28];
            *(float4*)&g_h[(size_t)s * D + j0]      = r0;
            *(float4*)&g_h[(size_t)s * D + j0 + 4]  = r1;
            *(float4*)&g_h[(size_t)s * D + j0 + 8]  = r2;
            *(float4*)&g_h[(size_t)s * D + j0 + 12] = r3;
            *(float4*)&g_h[(size_t)s * D + j0 + 16] = r4;
            *(float4*)&g_h[(size_t)s * D + j0 + 20] = r5;
            *(float4*)&g_h[(size_t)s * D + j0 + 24] = r6;
            *(float4*)&g_h[(size_t)s * D + j0 + 28] = r7;
            float4 q0 = *(float4*)&res[32];
            float4 q1 = *(float4*)&res[36];
            float4 q2 = *(float4*)&res[40];
            float4 q3 = *(float4*)&res[44];
            float4 q4 = *(float4*)&res[48];
            float4 q5 = *(float4*)&res[52];
            float4 q6 = *(float4*)&res[56];
            float4 q7 = *(float4*)&res[60];
            *(float4*)&g_h[((size_t)S + s) * D + j0]      = q0;
            *(float4*)&g_h[((size_t)S + s) * D + j0 + 4]  = q1;
            *(float4*)&g_h[((size_t)S + s) * D + j0 + 8]  = q2;
            *(float4*)&g_h[((size_t)S + s) * D + j0 + 12] = q3;
            *(float4*)&g_h[((size_t)S + s) * D + j0 + 16] = q4;
            *(float4*)&g_h[((size_t)S + s) * D + j0 + 20] = q5;
            *(float4*)&g_h[((size_t)S + s) * D + j0 + 24] = q6;
            *(float4*)&g_h[((size_t)S + s) * D + j0 + 28] = q7;
            st_rel_gpu(&g_flag[blockIdx.x * FPAD], s + 1);
        }
        if (s + 1 < S) {
            if (tid < RBLK) {
                while (flags[tid * FPAD] <= s) { }
            }
            __syncthreads();
        }
    }
}

// ---------------- attention ----------------
__global__ void scores_kernel(const float* __restrict__ q, const float* __restrict__ k) {
    int qt = blockIdx.x, kt = blockIdx.y;
    if (kt > qt) return;
    int bh = blockIdx.z;
    int b = bh >> 3, h = bh & 7;
    __shared__ __align__(16) float qs[32][68];
    __shared__ __align__(16) float ks[32][68];
    int tid = threadIdx.x;
    int tx = tid & 15, ty = tid >> 4;
    float acc[4][4] = {};
    size_t qbase = ((size_t)b * S + (size_t)qt * 64) * D + h * DHD;
    size_t kbase = ((size_t)b * S + (size_t)kt * 64) * D + h * DHD;
    for (int c0 = 0; c0 < DHD; c0 += 32) {
        for (int t = tid; t < 512; t += 256) {
            int r = t >> 3, c4 = (t & 7) * 4;
            float4 av = *(const float4*)&q[qbase + (size_t)r * D + c0 + c4];
            qs[c4 + 0][r] = av.x; qs[c4 + 1][r] = av.y;
            qs[c4 + 2][r] = av.z; qs[c4 + 3][r] = av.w;
            float4 bv = *(const float4*)&k[kbase + (size_t)r * D + c0 + c4];
            ks[c4 + 0][r] = bv.x; ks[c4 + 1][r] = bv.y;
            ks[c4 + 2][r] = bv.z; ks[c4 + 3][r] = bv.w;
        }
        __syncthreads();
#pragma unroll
        for (int kk = 0; kk < 32; kk++) {
            float4 a  = *(const float4*)&qs[kk][ty * 4];
            float4 bb = *(const float4*)&ks[kk][tx * 4];
            float ar[4] = {a.x, a.y, a.z, a.w};
            float br[4] = {bb.x, bb.y, bb.z, bb.w};
#pragma unroll
            for (int i = 0; i < 4; i++)
#pragma unroll
                for (int j = 0; j < 4; j++)
                    acc[i][j] = fmaf(ar[i], br[j], acc[i][j]);
        }
        __syncthreads();
    }
    const float scale = 0.088388347648318447f;  // 1/sqrt(128)
#pragma unroll
    for (int i = 0; i < 4; i++) {
        int srow = qt * 64 + ty * 4 + i;
        size_t rowbase = ((size_t)bh * S + srow) * S;
#pragma unroll
        for (int j = 0; j < 4; j++) {
            int tcol = kt * 64 + tx * 4 + j;
            float vsc = acc[i][j] * scale;
            if (tcol > srow) vsc = -3.0e38f;
            g_scores[rowbase + tcol] = vsc;
        }
    }
}

__global__ void softmax_kernel() {
    int rowid = blockIdx.x;
    int bh = rowid >> 11;
    int s = rowid & (S - 1);
    float* row = g_scores + ((size_t)bh * S + s) * S;
    int limit = ((s >> 6) + 1) << 6;
    int tid = threadIdx.x;
    int wid = tid >> 5, lane = tid & 31;
    __shared__ float sred[8];

    float m = -3.4e38f;
    for (int i = tid; i < limit; i += 256) m = fmaxf(m, row[i]);
#pragma unroll
    for (int o = 16; o; o >>= 1) m = fmaxf(m, __shfl_xor_sync(0xffffffffu, m, o));
    if (lane == 0) sred[wid] = m;
    __syncthreads();
    if (tid == 0) {
        float mm = sred[0];
        for (int i = 1; i < 8; i++) mm = fmaxf(mm, sred[i]);
        sred[0] = mm;
    }
    __syncthreads();
    m = sred[0];
    __syncthreads();

    float sum = 0.f;
    for (int i = tid; i < limit; i += 256) {
        float e = __expf(row[i] - m);
        row[i] = e;
        sum += e;
    }
#pragma unroll
    for (int o = 16; o; o >>= 1) sum += __shfl_xor_sync(0xffffffffu, sum, o);
    if (lane == 0) sred[wid] = sum;
    __syncthreads();
    if (tid == 0) {
        float t = 0.f;
        for (int i = 0; i < 8; i++) t += sred[i];
        sred[0] = t;
    }
    __syncthreads();
    float inv = 1.f / sred[0];
    for (int i = tid; i < limit; i += 256) row[i] *= inv;
    for (int i = limit + tid; i < S; i += 256) row[i] = 0.f;
}

// P@V with fused +h epilogue (ctx = P@V + h)
__global__ void pv_kernel(const float* __restrict__ v) {
    int qt = blockIdx.x, bh = blockIdx.y;
    int b = bh >> 3, h = bh & 7;
    __shared__ __align__(16) float pst[32][68];
    __shared__ __align__(16) float vs[32][128];
    int tid = threadIdx.x;
    int tx = tid & 15, ty = tid >> 4;
    float acc[4][8] = {};
    int s0 = qt * 64;
    int tmax = s0 + 64;
    for (int t0 = 0; t0 < tmax; t0 += 32) {
        for (int t = tid; t < 2048; t += 256) {
            int r = t >> 5, tc = t & 31;
            pst[tc][r] = g_scores[((size_t)bh * S + s0 + r) * S + t0 + tc];
        }
        for (int t = tid; t < 1024; t += 256) {
            int tr = t >> 5, c4 = (t & 31) * 4;
            *(float4*)&vs[tr][c4] =
                *(const float4*)&v[((size_t)b * S + t0 + tr) * D + h * DHD + c4];
        }
        __syncthreads();
#pragma unroll
        for (int kk = 0; kk < 32; kk++) {
            float4 a  = *(const float4*)&pst[kk][ty * 4];
            float4 b0 = *(const float4*)&vs[kk][tx * 8];
            float4 b1 = *(const float4*)&vs[kk][tx * 8 + 4];
            float ar[4] = {a.x, a.y, a.z, a.w};
            float br[8] = {b0.x, b0.y, b0.z, b0.w, b1.x, b1.y, b1.z, b1.w};
#pragma unroll
            for (int i = 0; i < 4; i++)
#pragma unroll
                for (int j = 0; j < 8; j++)
                    acc[i][j] = fmaf(ar[i], br[j], acc[i][j]);
        }
        __syncthreads();
    }
#pragma unroll
    for (int i = 0; i < 4; i++) {
        size_t obase = ((size_t)b * S + s0 + ty * 4 + i) * D + h * DHD + tx * 8;
#pragma unroll
        for (int j = 0; j < 8; j++) g_ctx[obase + j] = acc[i][j] + g_h[obase + j];
    }
}

// ---------------- launch ----------------
extern "C" void kernel_launch(void* const* d_in, const int* in_sizes, int n_in,
                              void* d_out, int out_size) {
    const float* x   = (const float*)d_in[0];
    const float* wn1 = (const float*)d_in[1];
    const float* wn2 = (const float*)d_in[2];
    const float* Wq  = (const float*)d_in[3];  const float* bq  = (const float*)d_in[4];
    const float* Wk  = (const float*)d_in[5];  const float* bk  = (const float*)d_in[6];
    const float* Wv  = (const float*)d_in[7];  const float* bv  = (const float*)d_in[8];
    const float* Wz  = (const float*)d_in[9];  const float* bz  = (const float*)d_in[10];
    const float* Wg  = (const float*)d_in[11]; const float* bg  = (const float*)d_in[12];
    const float* Wd  = (const float*)d_in[13]; const float* bd  = (const float*)d_in[14];
    const float* Wu  = (const float*)d_in[15]; const float* bu  = (const float*)d_in[16];
    const float* Wo  = (const float*)d_in[17]; const float* bo  = (const float*)d_in[18];
    const float* Wf1 = (const float*)d_in[19]; const float* bf1 = (const float*)d_in[20];
    const float* Wf2 = (const float*)d_in[21]; const float* bf2 = (const float*)d_in[22];
    float* out = (float*)d_out;

    float *xn, *q, *k, *v, *z, *dbuf, *gamma, *ctx, *y, *yn, *f1;
    cudaGetSymbolAddress((void**)&xn,    g_xn);
    cudaGetSymbolAddress((void**)&q,     g_q);
    cudaGetSymbolAddress((void**)&k,     g_k);
    cudaGetSymbolAddress((void**)&v,     g_v);
    cudaGetSymbolAddress((void**)&z,     g_z);
    cudaGetSymbolAddress((void**)&dbuf,  g_dbuf);
    cudaGetSymbolAddress((void**)&gamma, g_gamma);
    cudaGetSymbolAddress((void**)&ctx,   g_ctx);
    cudaGetSymbolAddress((void**)&y,     g_y);
    cudaGetSymbolAddress((void**)&yn,    g_yn);
    cudaGetSymbolAddress((void**)&f1,    g_f1);

    // raise recur smem limit (idempotent, host-side, not captured)
    cudaFuncSetAttribute(recur_kernel, cudaFuncAttributeMaxDynamicSharedMemorySize,
                         (int)RECUR_SMEM);

    dim3 gQKV(D / 128, M / 128);    // (8, 32)
    dim3 gR(RD / 128, M / 128);     // (2, 32)
    dim3 gF1(FD / 128, M / 128);    // (32, 32)

    // 1) pre-norm + projections
    rmsnorm_kernel<<<M, 256>>>(x, wn1, xn);
    sgemm_kernel<0, 0><<<gQKV, 256>>>(xn, Wq, bq, nullptr, q, D, D);
    sgemm_kernel<0, 0><<<gQKV, 256>>>(xn, Wk, bk, nullptr, k, D, D);
    sgemm_kernel<0, 0><<<gQKV, 256>>>(xn, Wv, bv, nullptr, v, D, D);
    sgemm_kernel<0, 0><<<gQKV, 256>>>(xn, Wz, bz, nullptr, z, D, D);

    // 2) decay gamma
    sgemm_kernel<1, 0><<<gR, 256>>>(z, Wd, bd, nullptr, dbuf, RD, D);
    sgemm_kernel<2, 0><<<gQKV, 256>>>(dbuf, Wu, bu, nullptr, gamma, D, RD);

    // 3) associative scan + k scaling
    scan_chunk_kernel<<<dim3(D / 128, NCH, B), 128>>>();
    scan_pref_kernel<<<dim3(D / 128, B), 128>>>();
    kscale_kernel<<<2048, 256>>>();

    // 4) sequential gated recurrence (32 persistent blocks, padded flag barrier)
    flag_reset_kernel<<<16, 256>>>();
    recur_kernel<<<RBLK, 1024, RECUR_SMEM>>>(Wg, bg);

    // 5) causal attention
    scores_kernel<<<dim3(S / 64, S / 64, BH), 256>>>(q, k);
    softmax_kernel<<<BH * S, 256>>>();
    pv_kernel<<<dim3(S / 64, BH), 256>>>(v);   // ctx = P@V + h fused

    // 6) residual + output projection
    sgemm_kernel<0, 1><<<gQKV, 256>>>(ctx, Wo, bo, x, y, D, D);

    // 7) FFN
    rmsnorm_kernel<<<M, 256>>>(y, wn2, yn);
    sgemm_kernel<3, 0><<<gF1, 256>>>(yn, Wf1, bf1, nullptr, f1, FD, D);
    sgemm_kernel<0, 1><<<gQKV, 256>>>(f1, Wf2, bf2, y, out, D, FD);
}

// round 12
// speedup vs baseline: 1.1168x; 1.1168x over previous
#include <cuda_runtime.h>
#include <math.h>

static constexpr int B  = 2;
static constexpr int S  = 2048;
static constexpr int D  = 1024;
static constexpr int H  = 8;
static constexpr int DHD = 128;
static constexpr int RD = 256;
static constexpr int FD = 4096;
static constexpr int M  = B * S;     // 4096
static constexpr int BH = B * H;     // 16
static constexpr int SCH = 128;      // scan chunk length
static constexpr int NCH = S / SCH;  // 16

// ---------------- scratch (static device globals; no allocations) ----------------
__device__ float g_xn[M * D];
__device__ float g_q[M * D];
__device__ float g_k[M * D];       // becomes k_scaled in place
__device__ float g_v[M * D];
__device__ float g_z[M * D];
__device__ float g_dbuf[M * RD];
__device__ float g_gamma[M * D];
__device__ float g_lga[M * D];
__device__ float g_csum[B * NCH * D];
__device__ float g_cpref[B * NCH * D];
__device__ float g_h[M * D];       // h_seq [B][S][D]
__device__ float g_ctx[M * D];
__device__ float g_y[M * D];
__device__ float g_yn[M * D];
__device__ float g_f1[M * FD];
__device__ float g_scores[(size_t)BH * S * S];   // 268 MB, softmax in place

// One flag per 128B L2 line (128 pollers/line = proven-safe per-slice load).
static constexpr int FPAD = 32;
__device__ int g_flag[128 * FPAD];

__device__ __forceinline__ void st_rel_gpu(int* p, int v) {
    asm volatile("st.release.gpu.global.b32 [%0], %1;" :: "l"(p), "r"(v) : "memory");
}

// ---------------- rmsnorm ----------------
__global__ void rmsnorm_kernel(const float* __restrict__ x, const float* __restrict__ w,
                               float* __restrict__ out) {
    int row = blockIdx.x;
    const float* xr = x + (size_t)row * D;
    float ss = 0.f;
    for (int i = threadIdx.x; i < D; i += 256) { float v = xr[i]; ss += v * v; }
#pragma unroll
    for (int o = 16; o; o >>= 1) ss += __shfl_xor_sync(0xffffffffu, ss, o);
    __shared__ float wsum[8];
    int wid = threadIdx.x >> 5, lane = threadIdx.x & 31;
    if (lane == 0) wsum[wid] = ss;
    __syncthreads();
    if (threadIdx.x == 0) {
        float t = 0.f;
        for (int i = 0; i < 8; i++) t += wsum[i];
        wsum[0] = t;
    }
    __syncthreads();
    float inv = 1.f / (sqrtf(wsum[0] / (float)D) + 1e-6f);
    for (int i = threadIdx.x; i < D; i += 256)
        out[(size_t)row * D + i] = w[i] * xr[i] * inv;
}

// ---------------- SGEMM (R9-proven): BK=8 double-buffered ----------------
template <int EPI, int RES>
__global__ void __launch_bounds__(256) sgemm_kernel(
    const float* __restrict__ A, const float* __restrict__ W,
    const float* __restrict__ bias, const float* __restrict__ Rp,
    float* __restrict__ C, int N, int K) {
    __shared__ __align__(16) float As[2][8][128];
    __shared__ __align__(16) float Ws[2][8][128];
    int bn = blockIdx.x * 128, bm = blockIdx.y * 128;
    int tid = threadIdx.x;
    int tx = tid & 15, ty = tid >> 4;
    int rowA = tid >> 1, colA = (tid & 1) * 4;
    int rowW = tid >> 5, colW = (tid & 31) * 4;
    float acc[8][8] = {};
    const float* Aptr = A + (size_t)(bm + rowA) * K + colA;
    const float* Wptr = W + (size_t)rowW * N + bn + colW;

    {
        float4 av = *(const float4*)(Aptr);
        float4 wv = *(const float4*)(Wptr);
        As[0][colA + 0][rowA] = av.x; As[0][colA + 1][rowA] = av.y;
        As[0][colA + 2][rowA] = av.z; As[0][colA + 3][rowA] = av.w;
        *(float4*)&Ws[0][rowW][colW] = wv;
    }
    __syncthreads();

    int buf = 0;
    for (int k0 = 0; k0 < K; k0 += 8) {
        bool more = (k0 + 8) < K;
        float4 av, wv;
        if (more) {
            av = *(const float4*)(Aptr + k0 + 8);
            wv = *(const float4*)(Wptr + (size_t)(k0 + 8) * N);
        }
#pragma unroll
        for (int kk = 0; kk < 8; kk++) {
            float a[8], bv[8];
            *(float4*)&a[0]  = *(const float4*)&As[buf][kk][ty * 8];
            *(float4*)&a[4]  = *(const float4*)&As[buf][kk][ty * 8 + 4];
            *(float4*)&bv[0] = *(const float4*)&Ws[buf][kk][tx * 8];
            *(float4*)&bv[4] = *(const float4*)&Ws[buf][kk][tx * 8 + 4];
#pragma unroll
            for (int i = 0; i < 8; i++)
#pragma unroll
                for (int j = 0; j < 8; j++)
                    acc[i][j] = fmaf(a[i], bv[j], acc[i][j]);
        }
        if (more) {
            int nb = buf ^ 1;
            As[nb][colA + 0][rowA] = av.x; As[nb][colA + 1][rowA] = av.y;
            As[nb][colA + 2][rowA] = av.z; As[nb][colA + 3][rowA] = av.w;
            *(float4*)&Ws[nb][rowW][colW] = wv;
        }
        __syncthreads();
        buf ^= 1;
    }

    int r0 = bm + ty * 8, c0 = bn + tx * 8;
#pragma unroll
    for (int i = 0; i < 8; i++) {
        size_t ro = (size_t)(r0 + i) * N;
#pragma unroll
        for (int j = 0; j < 8; j++) {
            float val = acc[i][j] + bias[c0 + j];
            if (EPI == 1) val = fmaxf(val, 0.f);
            if (EPI == 2) {
                val = 1.f / (1.f + expf(-val));
                val = fminf(fmaxf(val, 1e-6f), 1.f - 1e-6f);
            }
            if (EPI == 3) {
                float u = val;
                float t = tanhf(0.7978845608028654f * (u + 0.044715f * u * u * u));
                val = 0.5f * u * (1.f + t);
            }
            if (RES) val += Rp[ro + c0 + j];
            C[ro + c0 + j] = val;
        }
    }
}

// ---------------- scan ----------------
__global__ void scan_chunk_kernel() {
    int d = blockIdx.x * 128 + threadIdx.x;
    int ch = blockIdx.y, b = blockIdx.z;
    size_t base = ((size_t)b * S + (size_t)ch * SCH) * D + d;
    float acc = 0.f;
    for (int s = 0; s < SCH; s++) {
        size_t idx = base + (size_t)s * D;
        acc += logf(g_gamma[idx]);
        g_lga[idx] = acc;
    }
    g_csum[((size_t)b * NCH + ch) * D + d] = acc;
}

__global__ void scan_pref_kernel() {
    int d = blockIdx.x * 128 + threadIdx.x;
    int b = blockIdx.y;
    float run = 0.f;
    for (int c = 0; c < NCH; c++) {
        size_t idx = ((size_t)b * NCH + c) * D + d;
        g_cpref[idx] = run;
        run += g_csum[idx];
    }
}

__global__ void kscale_kernel() {
    const int n = M * D;
    for (int idx = blockIdx.x * 256 + threadIdx.x; idx < n; idx += gridDim.x * 256) {
        int b = idx >> 21;
        int s = (idx >> 10) & (S - 1);
        int d = idx & (D - 1);
        int ch = s >> 7;
        float pref = g_cpref[((size_t)b * NCH + ch) * D + d];
        g_k[idx] = g_k[idx] * expf(g_lga[idx] + pref);
    }
}

// ---------------- sequential recurrence (R9-proven: 128x256, padded flags) ----------------
__global__ void flag_reset_kernel() {
    for (int i = blockIdx.x * 256 + threadIdx.x; i < 128 * FPAD; i += gridDim.x * 256)
        g_flag[i] = 0;
}

__global__ void __launch_bounds__(256, 1) recur_kernel(const float* __restrict__ Wg,
                                                       const float* __restrict__ bg) {
    __shared__ __align__(16) float Wgs[8 * D];   // 32KB
    __shared__ __align__(16) float hs[2 * D];    // 8KB
    __shared__ __align__(16) float res[16];
    int tid = threadIdx.x;
    int j0 = blockIdx.x * 8;
    for (int idx = tid; idx < 8 * D; idx += 256) {
        int i = idx >> 3, c = idx & 7;
        Wgs[c * D + i] = Wg[(size_t)i * D + j0 + c];
    }
    __syncthreads();
    int w = tid >> 5, lane = tid & 31;
    int j = j0 + w;
    float bgj = bg[j];
    const float* Wcol = &Wgs[w * D];
    volatile int* flags = g_flag;

    float zv = 0.f, gv = 0.f;
    if (lane < 2) {
        size_t off0 = (size_t)lane * S * D + j;
        zv = g_z[off0];
        gv = g_gamma[off0];
    }

    for (int s = 0; s < S; s++) {
        float d0 = 0.f, d1 = 0.f;
        if (s > 0) {
            for (int t = tid; t < 512; t += 256) {
                int bsel = t >> 8;
                int i4 = (t & 255) * 4;
                *(float4*)&hs[bsel * D + i4] =
                    *(const float4*)&g_h[((size_t)(bsel ? S : 0) + s - 1) * D + i4];
            }
            __syncthreads();
#pragma unroll
            for (int r = 0; r < 8; r++) {
                int i4 = (r * 32 + lane) * 4;
                float4 wv = *(const float4*)&Wcol[i4];
                float4 h0 = *(const float4*)&hs[i4];
                float4 h1 = *(const float4*)&hs[D + i4];
                d0 = fmaf(h0.x, wv.x, d0); d1 = fmaf(h1.x, wv.x, d1);
                d0 = fmaf(h0.y, wv.y, d0); d1 = fmaf(h1.y, wv.y, d1);
                d0 = fmaf(h0.z, wv.z, d0); d1 = fmaf(h1.z, wv.z, d1);
                d0 = fmaf(h0.w, wv.w, d0); d1 = fmaf(h1.w, wv.w, d1);
            }
#pragma unroll
            for (int o = 16; o; o >>= 1) {
                d0 += __shfl_xor_sync(0xffffffffu, d0, o);
                d1 += __shfl_xor_sync(0xffffffffu, d1, o);
            }
        }
        if (lane < 2) {
            float dotv = lane ? d1 : d0;
            float hp = (s > 0) ? hs[lane * D + j] : 0.f;
            float sg = 1.f / (1.f + expf(-(dotv + bgj)));
            res[lane * 8 + w] = zv * sg + gv * hp;
        }
        __syncthreads();
        if (s + 1 < S && lane < 2) {
            size_t offn = ((size_t)lane * S + s + 1) * D + j;
            zv = g_z[offn];
            gv = g_gamma[offn];
        }
        if (tid == 0) {
            float4 r0 = *(float4*)&res[0];
            float4 r1 = *(float4*)&res[4];
            float4 r2 = *(float4*)&res[8];
            float4 r3 = *(float4*)&res[12];
            *(float4*)&g_h[(size_t)s * D + j0]           = r0;
            *(float4*)&g_h[(size_t)s * D + j0 + 4]       = r1;
            *(float4*)&g_h[((size_t)S + s) * D + j0]     = r2;
            *(float4*)&g_h[((size_t)S + s) * D + j0 + 4] = r3;
            st_rel_gpu(&g_flag[blockIdx.x * FPAD], s + 1);
        }
        if (s + 1 < S) {
            if (tid < 128) {
                while (flags[tid * FPAD] <= s) { }
            }
            __syncthreads();
        }
    }
}

// ---------------- attention ----------------
__global__ void scores_kernel(const float* __restrict__ q, const float* __restrict__ k) {
    int qt = blockIdx.x, kt = blockIdx.y;
    if (kt > qt) return;
    int bh = blockIdx.z;
    int b = bh >> 3, h = bh & 7;
    __shared__ __align__(16) float qs[32][68];
    __shared__ __align__(16) float ks[32][68];
    int tid = threadIdx.x;
    int tx = tid & 15, ty = tid >> 4;
    float acc[4][4] = {};
    size_t qbase = ((size_t)b * S + (size_t)qt * 64) * D + h * DHD;
    size_t kbase = ((size_t)b * S + (size_t)kt * 64) * D + h * DHD;
    for (int c0 = 0; c0 < DHD; c0 += 32) {
        for (int t = tid; t < 512; t += 256) {
            int r = t >> 3, c4 = (t & 7) * 4;
            float4 av = *(const float4*)&q[qbase + (size_t)r * D + c0 + c4];
            qs[c4 + 0][r] = av.x; qs[c4 + 1][r] = av.y;
            qs[c4 + 2][r] = av.z; qs[c4 + 3][r] = av.w;
            float4 bv = *(const float4*)&k[kbase + (size_t)r * D + c0 + c4];
            ks[c4 + 0][r] = bv.x; ks[c4 + 1][r] = bv.y;
            ks[c4 + 2][r] = bv.z; ks[c4 + 3][r] = bv.w;
        }
        __syncthreads();
#pragma unroll
        for (int kk = 0; kk < 32; kk++) {
            float4 a  = *(const float4*)&qs[kk][ty * 4];
            float4 bb = *(const float4*)&ks[kk][tx * 4];
            float ar[4] = {a.x, a.y, a.z, a.w};
            float br[4] = {bb.x, bb.y, bb.z, bb.w};
#pragma unroll
            for (int i = 0; i < 4; i++)
#pragma unroll
                for (int j = 0; j < 4; j++)
                    acc[i][j] = fmaf(ar[i], br[j], acc[i][j]);
        }
        __syncthreads();
    }
    const float scale = 0.088388347648318447f;  // 1/sqrt(128)
#pragma unroll
    for (int i = 0; i < 4; i++) {
        int srow = qt * 64 + ty * 4 + i;
        size_t rowbase = ((size_t)bh * S + srow) * S;
#pragma unroll
        for (int j = 0; j < 4; j++) {
            int tcol = kt * 64 + tx * 4 + j;
            float vsc = acc[i][j] * scale;
            if (tcol > srow) vsc = -3.0e38f;
            g_scores[rowbase + tcol] = vsc;
        }
    }
}

__global__ void softmax_kernel() {
    int rowid = blockIdx.x;
    int bh = rowid >> 11;
    int s = rowid & (S - 1);
    float* row = g_scores + ((size_t)bh * S + s) * S;
    int limit = ((s >> 6) + 1) << 6;
    int tid = threadIdx.x;
    int wid = tid >> 5, lane = tid & 31;
    __shared__ float sred[8];

    float m = -3.4e38f;
    for (int i = tid; i < limit; i += 256) m = fmaxf(m, row[i]);
#pragma unroll
    for (int o = 16; o; o >>= 1) m = fmaxf(m, __shfl_xor_sync(0xffffffffu, m, o));
    if (lane == 0) sred[wid] = m;
    __syncthreads();
    if (tid == 0) {
        float mm = sred[0];
        for (int i = 1; i < 8; i++) mm = fmaxf(mm, sred[i]);
        sred[0] = mm;
    }
    __syncthreads();
    m = sred[0];
    __syncthreads();

    float sum = 0.f;
    for (int i = tid; i < limit; i += 256) {
        float e = __expf(row[i] - m);
        row[i] = e;
        sum += e;
    }
#pragma unroll
    for (int o = 16; o; o >>= 1) sum += __shfl_xor_sync(0xffffffffu, sum, o);
    if (lane == 0) sred[wid] = sum;
    __syncthreads();
    if (tid == 0) {
        float t = 0.f;
        for (int i = 0; i < 8; i++) t += sred[i];
        sred[0] = t;
    }
    __syncthreads();
    float inv = 1.f / sred[0];
    for (int i = tid; i < limit; i += 256) row[i] *= inv;
    for (int i = limit + tid; i < S; i += 256) row[i] = 0.f;
}

// P@V with fused +h epilogue (ctx = P@V + h)
__global__ void pv_kernel(const float* __restrict__ v) {
    int qt = blockIdx.x, bh = blockIdx.y;
    int b = bh >> 3, h = bh & 7;
    __shared__ __align__(16) float pst[32][68];
    __shared__ __align__(16) float vs[32][128];
    int tid = threadIdx.x;
    int tx = tid & 15, ty = tid >> 4;
    float acc[4][8] = {};
    int s0 = qt * 64;
    int tmax = s0 + 64;
    for (int t0 = 0; t0 < tmax; t0 += 32) {
        for (int t = tid; t < 2048; t += 256) {
            int r = t >> 5, tc = t & 31;
            pst[tc][r] = g_scores[((size_t)bh * S + s0 + r) * S + t0 + tc];
        }
        for (int t = tid; t < 1024; t += 256) {
            int tr = t >> 5, c4 = (t & 31) * 4;
            *(float4*)&vs[tr][c4] =
                *(const float4*)&v[((size_t)b * S + t0 + tr) * D + h * DHD + c4];
        }
        __syncthreads();
#pragma unroll
        for (int kk = 0; kk < 32; kk++) {
            float4 a  = *(const float4*)&pst[kk][ty * 4];
            float4 b0 = *(const float4*)&vs[kk][tx * 8];
            float4 b1 = *(const float4*)&vs[kk][tx * 8 + 4];
            float ar[4] = {a.x, a.y, a.z, a.w};
            float br[8] = {b0.x, b0.y, b0.z, b0.w, b1.x, b1.y, b1.z, b1.w};
#pragma unroll
            for (int i = 0; i < 4; i++)
#pragma unroll
                for (int j = 0; j < 8; j++)
                    acc[i][j] = fmaf(ar[i], br[j], acc[i][j]);
        }
        __syncthreads();
    }
#pragma unroll
    for (int i = 0; i < 4; i++) {
        size_t obase = ((size_t)b * S + s0 + ty * 4 + i) * D + h * DHD + tx * 8;
#pragma unroll
        for (int j = 0; j < 8; j++) g_ctx[obase + j] = acc[i][j] + g_h[obase + j];
    }
}

// ---------------- launch ----------------
extern "C" void kernel_launch(void* const* d_in, const int* in_sizes, int n_in,
                              void* d_out, int out_size) {
    const float* x   = (const float*)d_in[0];
    const float* wn1 = (const float*)d_in[1];
    const float* wn2 = (const float*)d_in[2];
    const float* Wq  = (const float*)d_in[3];  const float* bq  = (const float*)d_in[4];
    const float* Wk  = (const float*)d_in[5];  const float* bk  = (const float*)d_in[6];
    const float* Wv  = (const float*)d_in[7];  const float* bv  = (const float*)d_in[8];
    const float* Wz  = (const float*)d_in[9];  const float* bz  = (const float*)d_in[10];
    const float* Wg  = (const float*)d_in[11]; const float* bg  = (const float*)d_in[12];
    const float* Wd  = (const float*)d_in[13]; const float* bd  = (const float*)d_in[14];
    const float* Wu  = (const float*)d_in[15]; const float* bu  = (const float*)d_in[16];
    const float* Wo  = (const float*)d_in[17]; const float* bo  = (const float*)d_in[18];
    const float* Wf1 = (const float*)d_in[19]; const float* bf1 = (const float*)d_in[20];
    const float* Wf2 = (const float*)d_in[21]; const float* bf2 = (const float*)d_in[22];
    float* out = (float*)d_out;

    float *xn, *q, *k, *v, *z, *dbuf, *gamma, *ctx, *y, *yn, *f1;
    cudaGetSymbolAddress((void**)&xn,    g_xn);
    cudaGetSymbolAddress((void**)&q,     g_q);
    cudaGetSymbolAddress((void**)&k,     g_k);
    cudaGetSymbolAddress((void**)&v,     g_v);
    cudaGetSymbolAddress((void**)&z,     g_z);
    cudaGetSymbolAddress((void**)&dbuf,  g_dbuf);
    cudaGetSymbolAddress((void**)&gamma, g_gamma);
    cudaGetSymbolAddress((void**)&ctx,   g_ctx);
    cudaGetSymbolAddress((void**)&y,     g_y);
    cudaGetSymbolAddress((void**)&yn,    g_yn);
    cudaGetSymbolAddress((void**)&f1,    g_f1);

    dim3 gQKV(D / 128, M / 128);    // (8, 32)
    dim3 gR(RD / 128, M / 128);     // (2, 32)
    dim3 gF1(FD / 128, M / 128);    // (32, 32)

    // 1) pre-norm + projections
    rmsnorm_kernel<<<M, 256>>>(x, wn1, xn);
    sgemm_kernel<0, 0><<<gQKV, 256>>>(xn, Wq, bq, nullptr, q, D, D);
    sgemm_kernel<0, 0><<<gQKV, 256>>>(xn, Wk, bk, nullptr, k, D, D);
    sgemm_kernel<0, 0><<<gQKV, 256>>>(xn, Wv, bv, nullptr, v, D, D);
    sgemm_kernel<0, 0><<<gQKV, 256>>>(xn, Wz, bz, nullptr, z, D, D);

    // 2) decay gamma
    sgemm_kernel<1, 0><<<gR, 256>>>(z, Wd, bd, nullptr, dbuf, RD, D);
    sgemm_kernel<2, 0><<<gQKV, 256>>>(dbuf, Wu, bu, nullptr, gamma, D, RD);

    // 3) associative scan + k scaling
    scan_chunk_kernel<<<dim3(D / 128, NCH, B), 128>>>();
    scan_pref_kernel<<<dim3(D / 128, B), 128>>>();
    kscale_kernel<<<2048, 256>>>();

    // 4+5) FORK: recurrence (default stream) || scores+softmax (stream 2).
    // scores/softmax depend only on q/k_scaled; recur depends only on z/gamma.
    // Events translate into graph dependencies during capture; stream/event
    // objects are host-side (no device memory) and are created per call
    // (kernel_launch only runs twice: correctness + capture).
    cudaStream_t s2;
    cudaEvent_t ev_fork, ev_join;
    cudaStreamCreateWithFlags(&s2, cudaStreamNonBlocking);
    cudaEventCreateWithFlags(&ev_fork, cudaEventDisableTiming);
    cudaEventCreateWithFlags(&ev_join, cudaEventDisableTiming);

    cudaEventRecord(ev_fork, 0);               // after kscale on default stream
    cudaStreamWaitEvent(s2, ev_fork, 0);
    scores_kernel<<<dim3(S / 64, S / 64, BH), 256, 0, s2>>>(q, k);
    softmax_kernel<<<BH * S, 256, 0, s2>>>();
    cudaEventRecord(ev_join, s2);

    flag_reset_kernel<<<16, 256>>>();
    recur_kernel<<<128, 256>>>(Wg, bg);

    cudaStreamWaitEvent(0, ev_join, 0);        // join before pv (needs probs + h)
    pv_kernel<<<dim3(S / 64, BH), 256>>>(v);   // ctx = P@V + h fused

    // 6) residual + output projection
    sgemm_kernel<0, 1><<<gQKV, 256>>>(ctx, Wo, bo, x, y, D, D);

    // 7) FFN
    rmsnorm_kernel<<<M, 256>>>(y, wn2, yn);
    sgemm_kernel<3, 0><<<gF1, 256>>>(yn, Wf1, bf1, nullptr, f1, FD, D);
    sgemm_kernel<0, 1><<<gQKV, 256>>>(f1, Wf2, bf2, y, out, D, FD);
}

// round 13
// speedup vs baseline: 1.2320x; 1.1031x over previous
#include <cuda_runtime.h>
#include <math.h>

static constexpr int B  = 2;
static constexpr int S  = 2048;
static constexpr int D  = 1024;
static constexpr int H  = 8;
static constexpr int DHD = 128;
static constexpr int RD = 256;
static constexpr int FD = 4096;
static constexpr int M  = B * S;     // 4096
static constexpr int BH = B * H;     // 16
static constexpr int SCH = 128;      // scan chunk length
static constexpr int NCH = S / SCH;  // 16

// ---------------- scratch (static device globals; no allocations) ----------------
__device__ float g_xn[M * D];
__device__ float g_q[M * D];
__device__ float g_k[M * D];       // becomes k_scaled in place
__device__ float g_v[M * D];
__device__ float g_z[M * D];
__device__ float g_dbuf[M * RD];
__device__ float g_gamma[M * D];
__device__ float g_lga[M * D];
__device__ float g_csum[B * NCH * D];
__device__ float g_cpref[B * NCH * D];
__device__ float g_h[M * D];       // h_seq [B][S][D]
__device__ float g_ctx[M * D];
__device__ float g_y[M * D];
__device__ float g_yn[M * D];
__device__ float g_f1[M * FD];
__device__ float g_scores[(size_t)BH * S * S];   // 268 MB, softmax in place

// One flag per 128B L2 line (128 pollers/line = proven-safe per-slice load).
static constexpr int FPAD = 32;
__device__ int g_flag[128 * FPAD];

__device__ __forceinline__ void st_rel_gpu(int* p, int v) {
    asm volatile("st.release.gpu.global.b32 [%0], %1;" :: "l"(p), "r"(v) : "memory");
}

// ---------------- rmsnorm ----------------
__global__ void rmsnorm_kernel(const float* __restrict__ x, const float* __restrict__ w,
                               float* __restrict__ out) {
    int row = blockIdx.x;
    const float* xr = x + (size_t)row * D;
    float ss = 0.f;
    for (int i = threadIdx.x; i < D; i += 256) { float v = xr[i]; ss += v * v; }
#pragma unroll
    for (int o = 16; o; o >>= 1) ss += __shfl_xor_sync(0xffffffffu, ss, o);
    __shared__ float wsum[8];
    int wid = threadIdx.x >> 5, lane = threadIdx.x & 31;
    if (lane == 0) wsum[wid] = ss;
    __syncthreads();
    if (threadIdx.x == 0) {
        float t = 0.f;
        for (int i = 0; i < 8; i++) t += wsum[i];
        wsum[0] = t;
    }
    __syncthreads();
    float inv = 1.f / (sqrtf(wsum[0] / (float)D) + 1e-6f);
    for (int i = threadIdx.x; i < D; i += 256)
        out[(size_t)row * D + i] = w[i] * xr[i] * inv;
}

// ---------------- SGEMM (R9-proven): BK=8 double-buffered ----------------
template <int EPI, int RES>
__global__ void __launch_bounds__(256) sgemm_kernel(
    const float* __restrict__ A, const float* __restrict__ W,
    const float* __restrict__ bias, const float* __restrict__ Rp,
    float* __restrict__ C, int N, int K) {
    __shared__ __align__(16) float As[2][8][128];
    __shared__ __align__(16) float Ws[2][8][128];
    int bn = blockIdx.x * 128, bm = blockIdx.y * 128;
    int tid = threadIdx.x;
    int tx = tid & 15, ty = tid >> 4;
    int rowA = tid >> 1, colA = (tid & 1) * 4;
    int rowW = tid >> 5, colW = (tid & 31) * 4;
    float acc[8][8] = {};
    const float* Aptr = A + (size_t)(bm + rowA) * K + colA;
    const float* Wptr = W + (size_t)rowW * N + bn + colW;

    {
        float4 av = *(const float4*)(Aptr);
        float4 wv = *(const float4*)(Wptr);
        As[0][colA + 0][rowA] = av.x; As[0][colA + 1][rowA] = av.y;
        As[0][colA + 2][rowA] = av.z; As[0][colA + 3][rowA] = av.w;
        *(float4*)&Ws[0][rowW][colW] = wv;
    }
    __syncthreads();

    int buf = 0;
    for (int k0 = 0; k0 < K; k0 += 8) {
        bool more = (k0 + 8) < K;
        float4 av, wv;
        if (more) {
            av = *(const float4*)(Aptr + k0 + 8);
            wv = *(const float4*)(Wptr + (size_t)(k0 + 8) * N);
        }
#pragma unroll
        for (int kk = 0; kk < 8; kk++) {
            float a[8], bv[8];
            *(float4*)&a[0]  = *(const float4*)&As[buf][kk][ty * 8];
            *(float4*)&a[4]  = *(const float4*)&As[buf][kk][ty * 8 + 4];
            *(float4*)&bv[0] = *(const float4*)&Ws[buf][kk][tx * 8];
            *(float4*)&bv[4] = *(const float4*)&Ws[buf][kk][tx * 8 + 4];
#pragma unroll
            for (int i = 0; i < 8; i++)
#pragma unroll
                for (int j = 0; j < 8; j++)
                    acc[i][j] = fmaf(a[i], bv[j], acc[i][j]);
        }
        if (more) {
            int nb = buf ^ 1;
            As[nb][colA + 0][rowA] = av.x; As[nb][colA + 1][rowA] = av.y;
            As[nb][colA + 2][rowA] = av.z; As[nb][colA + 3][rowA] = av.w;
            *(float4*)&Ws[nb][rowW][colW] = wv;
        }
        __syncthreads();
        buf ^= 1;
    }

    int r0 = bm + ty * 8, c0 = bn + tx * 8;
#pragma unroll
    for (int i = 0; i < 8; i++) {
        size_t ro = (size_t)(r0 + i) * N;
#pragma unroll
        for (int j = 0; j < 8; j++) {
            float val = acc[i][j] + bias[c0 + j];
            if (EPI == 1) val = fmaxf(val, 0.f);
            if (EPI == 2) {
                val = 1.f / (1.f + expf(-val));
                val = fminf(fmaxf(val, 1e-6f), 1.f - 1e-6f);
            }
            if (EPI == 3) {
                float u = val;
                float t = tanhf(0.7978845608028654f * (u + 0.044715f * u * u * u));
                val = 0.5f * u * (1.f + t);
            }
            if (RES) val += Rp[ro + c0 + j];
            C[ro + c0 + j] = val;
        }
    }
}

// ---------------- batched QKVZ SGEMM: one launch, gridDim.z selects W/b/C ----------------
__global__ void __launch_bounds__(256) sgemm_qkvz_kernel(
    const float* __restrict__ A,
    const float* __restrict__ W0, const float* __restrict__ W1,
    const float* __restrict__ W2, const float* __restrict__ W3,
    const float* __restrict__ b0, const float* __restrict__ b1,
    const float* __restrict__ b2, const float* __restrict__ b3,
    float* __restrict__ C0, float* __restrict__ C1,
    float* __restrict__ C2, float* __restrict__ C3) {
    const int N = D, K = D;
    int zi = blockIdx.z;
    const float* W    = (zi == 0) ? W0 : (zi == 1) ? W1 : (zi == 2) ? W2 : W3;
    const float* bias = (zi == 0) ? b0 : (zi == 1) ? b1 : (zi == 2) ? b2 : b3;
    float* C          = (zi == 0) ? C0 : (zi == 1) ? C1 : (zi == 2) ? C2 : C3;

    __shared__ __align__(16) float As[2][8][128];
    __shared__ __align__(16) float Ws[2][8][128];
    int bn = blockIdx.x * 128, bm = blockIdx.y * 128;
    int tid = threadIdx.x;
    int tx = tid & 15, ty = tid >> 4;
    int rowA = tid >> 1, colA = (tid & 1) * 4;
    int rowW = tid >> 5, colW = (tid & 31) * 4;
    float acc[8][8] = {};
    const float* Aptr = A + (size_t)(bm + rowA) * K + colA;
    const float* Wptr = W + (size_t)rowW * N + bn + colW;

    {
        float4 av = *(const float4*)(Aptr);
        float4 wv = *(const float4*)(Wptr);
        As[0][colA + 0][rowA] = av.x; As[0][colA + 1][rowA] = av.y;
        As[0][colA + 2][rowA] = av.z; As[0][colA + 3][rowA] = av.w;
        *(float4*)&Ws[0][rowW][colW] = wv;
    }
    __syncthreads();

    int buf = 0;
    for (int k0 = 0; k0 < K; k0 += 8) {
        bool more = (k0 + 8) < K;
        float4 av, wv;
        if (more) {
            av = *(const float4*)(Aptr + k0 + 8);
            wv = *(const float4*)(Wptr + (size_t)(k0 + 8) * N);
        }
#pragma unroll
        for (int kk = 0; kk < 8; kk++) {
            float a[8], bv[8];
            *(float4*)&a[0]  = *(const float4*)&As[buf][kk][ty * 8];
            *(float4*)&a[4]  = *(const float4*)&As[buf][kk][ty * 8 + 4];
            *(float4*)&bv[0] = *(const float4*)&Ws[buf][kk][tx * 8];
            *(float4*)&bv[4] = *(const float4*)&Ws[buf][kk][tx * 8 + 4];
#pragma unroll
            for (int i = 0; i < 8; i++)
#pragma unroll
                for (int j = 0; j < 8; j++)
                    acc[i][j] = fmaf(a[i], bv[j], acc[i][j]);
        }
        if (more) {
            int nb = buf ^ 1;
            As[nb][colA + 0][rowA] = av.x; As[nb][colA + 1][rowA] = av.y;
            As[nb][colA + 2][rowA] = av.z; As[nb][colA + 3][rowA] = av.w;
            *(float4*)&Ws[nb][rowW][colW] = wv;
        }
        __syncthreads();
        buf ^= 1;
    }

    int r0 = bm + ty * 8, c0 = bn + tx * 8;
#pragma unroll
    for (int i = 0; i < 8; i++) {
        size_t ro = (size_t)(r0 + i) * N;
#pragma unroll
        for (int j = 0; j < 8; j++)
            C[ro + c0 + j] = acc[i][j] + bias[c0 + j];
    }
}

// ---------------- scan ----------------
__global__ void scan_chunk_kernel() {
    int d = blockIdx.x * 128 + threadIdx.x;
    int ch = blockIdx.y, b = blockIdx.z;
    size_t base = ((size_t)b * S + (size_t)ch * SCH) * D + d;
    float acc = 0.f;
    for (int s = 0; s < SCH; s++) {
        size_t idx = base + (size_t)s * D;
        acc += logf(g_gamma[idx]);
        g_lga[idx] = acc;
    }
    g_csum[((size_t)b * NCH + ch) * D + d] = acc;
}

__global__ void scan_pref_kernel() {
    int d = blockIdx.x * 128 + threadIdx.x;
    int b = blockIdx.y;
    float run = 0.f;
    for (int c = 0; c < NCH; c++) {
        size_t idx = ((size_t)b * NCH + c) * D + d;
        g_cpref[idx] = run;
        run += g_csum[idx];
    }
}

__global__ void kscale_kernel() {
    const int n = M * D;
    for (int idx = blockIdx.x * 256 + threadIdx.x; idx < n; idx += gridDim.x * 256) {
        int b = idx >> 21;
        int s = (idx >> 10) & (S - 1);
        int d = idx & (D - 1);
        int ch = s >> 7;
        float pref = g_cpref[((size_t)b * NCH + ch) * D + d];
        g_k[idx] = g_k[idx] * expf(g_lga[idx] + pref);
    }
}

// ---------------- sequential recurrence v6: fused poll + h-fetch ----------------
// vs R9: each poller thread, upon seeing ITS flag advance, immediately loads that
// block's 16-float h segment into smem -- fetches overlap straggler waiting and
// the separate staging RTT disappears. Compiler fence stops LDG hoisting above
// the volatile spin; HW ordering is safe (writer's st.release pushed data to L2
// before the flag; data addresses are step-fresh, never L1-cached).
__global__ void flag_reset_kernel() {
    for (int i = blockIdx.x * 256 + threadIdx.x; i < 128 * FPAD; i += gridDim.x * 256)
        g_flag[i] = 0;
}

__global__ void __launch_bounds__(256, 1) recur_kernel(const float* __restrict__ Wg,
                                                       const float* __restrict__ bg) {
    __shared__ __align__(16) float Wgs[8 * D];   // 32KB
    __shared__ __align__(16) float hs[2 * D];    // 8KB: h_{s-1} both batches
    __shared__ __align__(16) float res[16];
    int tid = threadIdx.x;
    int j0 = blockIdx.x * 8;
    for (int idx = tid; idx < 8 * D; idx += 256) {
        int i = idx >> 3, c = idx & 7;
        Wgs[c * D + i] = Wg[(size_t)i * D + j0 + c];
    }
    __syncthreads();
    int w = tid >> 5, lane = tid & 31;
    int j = j0 + w;
    float bgj = bg[j];
    const float* Wcol = &Wgs[w * D];
    volatile int* flags = g_flag;

    float zv = 0.f, gv = 0.f;
    if (lane < 2) {
        size_t off0 = (size_t)lane * S * D + j;
        zv = g_z[off0];
        gv = g_gamma[off0];
    }

    for (int s = 0; s < S; s++) {
        float d0 = 0.f, d1 = 0.f;
        if (s > 0) {
            // hs already holds h_{s-1} (loaded at the end of the previous iter)
#pragma unroll
            for (int r = 0; r < 8; r++) {
                int i4 = (r * 32 + lane) * 4;
                float4 wv = *(const float4*)&Wcol[i4];
                float4 h0 = *(const float4*)&hs[i4];
                float4 h1 = *(const float4*)&hs[D + i4];
                d0 = fmaf(h0.x, wv.x, d0); d1 = fmaf(h1.x, wv.x, d1);
                d0 = fmaf(h0.y, wv.y, d0); d1 = fmaf(h1.y, wv.y, d1);
                d0 = fmaf(h0.z, wv.z, d0); d1 = fmaf(h1.z, wv.z, d1);
                d0 = fmaf(h0.w, wv.w, d0); d1 = fmaf(h1.w, wv.w, d1);
            }
#pragma unroll
            for (int o = 16; o; o >>= 1) {
                d0 += __shfl_xor_sync(0xffffffffu, d0, o);
                d1 += __shfl_xor_sync(0xffffffffu, d1, o);
            }
        }
        if (lane < 2) {
            float dotv = lane ? d1 : d0;
            float hp = (s > 0) ? hs[lane * D + j] : 0.f;
            float sg = 1.f / (1.f + expf(-(dotv + bgj)));
            res[lane * 8 + w] = zv * sg + gv * hp;
        }
        __syncthreads();   // res visible to tid0; all reads of hs complete
        // prefetch z/gamma for s+1 (hides behind poll)
        if (s + 1 < S && lane < 2) {
            size_t offn = ((size_t)lane * S + s + 1) * D + j;
            zv = g_z[offn];
            gv = g_gamma[offn];
        }
        // tid0: coalesced h store + release flag
        if (tid == 0) {
            float4 r0 = *(float4*)&res[0];
            float4 r1 = *(float4*)&res[4];
            float4 r2 = *(float4*)&res[8];
            float4 r3 = *(float4*)&res[12];
            *(float4*)&g_h[(size_t)s * D + j0]           = r0;
            *(float4*)&g_h[(size_t)s * D + j0 + 4]       = r1;
            *(float4*)&g_h[((size_t)S + s) * D + j0]     = r2;
            *(float4*)&g_h[((size_t)S + s) * D + j0 + 4] = r3;
            st_rel_gpu(&g_flag[blockIdx.x * FPAD], s + 1);
        }
        if (s + 1 < S) {
            if (tid < 128) {
                while (flags[tid * FPAD] <= s) { }
                asm volatile("" ::: "memory");    // no hoisting loads above spin
                int jb = tid * 8;
                *(float4*)&hs[jb]         = *(const float4*)&g_h[(size_t)s * D + jb];
                *(float4*)&hs[jb + 4]     = *(const float4*)&g_h[(size_t)s * D + jb + 4];
                *(float4*)&hs[D + jb]     = *(const float4*)&g_h[((size_t)S + s) * D + jb];
                *(float4*)&hs[D + jb + 4] = *(const float4*)&g_h[((size_t)S + s) * D + jb + 4];
            }
            __syncthreads();
        }
    }
}

// ---------------- attention ----------------
__global__ void scores_kernel(const float* __restrict__ q, const float* __restrict__ k) {
    int qt = blockIdx.x, kt = blockIdx.y;
    if (kt > qt) return;
    int bh = blockIdx.z;
    int b = bh >> 3, h = bh & 7;
    __shared__ __align__(16) float qs[32][68];
    __shared__ __align__(16) float ks[32][68];
    int tid = threadIdx.x;
    int tx = tid & 15, ty = tid >> 4;
    float acc[4][4] = {};
    size_t qbase = ((size_t)b * S + (size_t)qt * 64) * D + h * DHD;
    size_t kbase = ((size_t)b * S + (size_t)kt * 64) * D + h * DHD;
    for (int c0 = 0; c0 < DHD; c0 += 32) {
        for (int t = tid; t < 512; t += 256) {
            int r = t >> 3, c4 = (t & 7) * 4;
            float4 av = *(const float4*)&q[qbase + (size_t)r * D + c0 + c4];
            qs[c4 + 0][r] = av.x; qs[c4 + 1][r] = av.y;
            qs[c4 + 2][r] = av.z; qs[c4 + 3][r] = av.w;
            float4 bv = *(const float4*)&k[kbase + (size_t)r * D + c0 + c4];
            ks[c4 + 0][r] = bv.x; ks[c4 + 1][r] = bv.y;
            ks[c4 + 2][r] = bv.z; ks[c4 + 3][r] = bv.w;
        }
        __syncthreads();
#pragma unroll
        for (int kk = 0; kk < 32; kk++) {
            float4 a  = *(const float4*)&qs[kk][ty * 4];
            float4 bb = *(const float4*)&ks[kk][tx * 4];
            float ar[4] = {a.x, a.y, a.z, a.w};
            float br[4] = {bb.x, bb.y, bb.z, bb.w};
#pragma unroll
            for (int i = 0; i < 4; i++)
#pragma unroll
                for (int j = 0; j < 4; j++)
                    acc[i][j] = fmaf(ar[i], br[j], acc[i][j]);
        }
        __syncthreads();
    }
    const float scale = 0.088388347648318447f;  // 1/sqrt(128)
#pragma unroll
    for (int i = 0; i < 4; i++) {
        int srow = qt * 64 + ty * 4 + i;
        size_t rowbase = ((size_t)bh * S + srow) * S;
#pragma unroll
        for (int j = 0; j < 4; j++) {
            int tcol = kt * 64 + tx * 4 + j;
            float vsc = acc[i][j] * scale;
            if (tcol > srow) vsc = -3.0e38f;
            g_scores[rowbase + tcol] = vsc;
        }
    }
}

__global__ void softmax_kernel() {
    int rowid = blockIdx.x;
    int bh = rowid >> 11;
    int s = rowid & (S - 1);
    float* row = g_scores + ((size_t)bh * S + s) * S;
    int limit = ((s >> 6) + 1) << 6;
    int tid = threadIdx.x;
    int wid = tid >> 5, lane = tid & 31;
    __shared__ float sred[8];

    float m = -3.4e38f;
    for (int i = tid; i < limit; i += 256) m = fmaxf(m, row[i]);
#pragma unroll
    for (int o = 16; o; o >>= 1) m = fmaxf(m, __shfl_xor_sync(0xffffffffu, m, o));
    if (lane == 0) sred[wid] = m;
    __syncthreads();
    if (tid == 0) {
        float mm = sred[0];
        for (int i = 1; i < 8; i++) mm = fmaxf(mm, sred[i]);
        sred[0] = mm;
    }
    __syncthreads();
    m = sred[0];
    __syncthreads();

    float sum = 0.f;
    for (int i = tid; i < limit; i += 256) {
        float e = __expf(row[i] - m);
        row[i] = e;
        sum += e;
    }
#pragma unroll
    for (int o = 16; o; o >>= 1) sum += __shfl_xor_sync(0xffffffffu, sum, o);
    if (lane == 0) sred[wid] = sum;
    __syncthreads();
    if (tid == 0) {
        float t = 0.f;
        for (int i = 0; i < 8; i++) t += sred[i];
        sred[0] = t;
    }
    __syncthreads();
    float inv = 1.f / sred[0];
    for (int i = tid; i < limit; i += 256) row[i] *= inv;
    for (int i = limit + tid; i < S; i += 256) row[i] = 0.f;
}

// P@V with fused +h epilogue (ctx = P@V + h)
__global__ void pv_kernel(const float* __restrict__ v) {
    int qt = blockIdx.x, bh = blockIdx.y;
    int b = bh >> 3, h = bh & 7;
    __shared__ __align__(16) float pst[32][68];
    __shared__ __align__(16) float vs[32][128];
    int tid = threadIdx.x;
    int tx = tid & 15, ty = tid >> 4;
    float acc[4][8] = {};
    int s0 = qt * 64;
    int tmax = s0 + 64;
    for (int t0 = 0; t0 < tmax; t0 += 32) {
        for (int t = tid; t < 2048; t += 256) {
            int r = t >> 5, tc = t & 31;
            pst[tc][r] = g_scores[((size_t)bh * S + s0 + r) * S + t0 + tc];
        }
        for (int t = tid; t < 1024; t += 256) {
            int tr = t >> 5, c4 = (t & 31) * 4;
            *(float4*)&vs[tr][c4] =
                *(const float4*)&v[((size_t)b * S + t0 + tr) * D + h * DHD + c4];
        }
        __syncthreads();
#pragma unroll
        for (int kk = 0; kk < 32; kk++) {
            float4 a  = *(const float4*)&pst[kk][ty * 4];
            float4 b0 = *(const float4*)&vs[kk][tx * 8];
            float4 b1 = *(const float4*)&vs[kk][tx * 8 + 4];
            float ar[4] = {a.x, a.y, a.z, a.w};
            float br[8] = {b0.x, b0.y, b0.z, b0.w, b1.x, b1.y, b1.z, b1.w};
#pragma unroll
            for (int i = 0; i < 4; i++)
#pragma unroll
                for (int j = 0; j < 8; j++)
                    acc[i][j] = fmaf(ar[i], br[j], acc[i][j]);
        }
        __syncthreads();
    }
#pragma unroll
    for (int i = 0; i < 4; i++) {
        size_t obase = ((size_t)b * S + s0 + ty * 4 + i) * D + h * DHD + tx * 8;
#pragma unroll
        for (int j = 0; j < 8; j++) g_ctx[obase + j] = acc[i][j] + g_h[obase + j];
    }
}

// ---------------- launch ----------------
extern "C" void kernel_launch(void* const* d_in, const int* in_sizes, int n_in,
                              void* d_out, int out_size) {
    const float* x   = (const float*)d_in[0];
    const float* wn1 = (const float*)d_in[1];
    const float* wn2 = (const float*)d_in[2];
    const float* Wq  = (const float*)d_in[3];  const float* bq  = (const float*)d_in[4];
    const float* Wk  = (const float*)d_in[5];  const float* bk  = (const float*)d_in[6];
    const float* Wv  = (const float*)d_in[7];  const float* bv  = (const float*)d_in[8];
    const float* Wz  = (const float*)d_in[9];  const float* bz  = (const float*)d_in[10];
    const float* Wg  = (const float*)d_in[11]; const float* bg  = (const float*)d_in[12];
    const float* Wd  = (const float*)d_in[13]; const float* bd  = (const float*)d_in[14];
    const float* Wu  = (const float*)d_in[15]; const float* bu  = (const float*)d_in[16];
    const float* Wo  = (const float*)d_in[17]; const float* bo  = (const float*)d_in[18];
    const float* Wf1 = (const float*)d_in[19]; const float* bf1 = (const float*)d_in[20];
    const float* Wf2 = (const float*)d_in[21]; const float* bf2 = (const float*)d_in[22];
    float* out = (float*)d_out;

    float *xn, *q, *k, *v, *z, *dbuf, *gamma, *ctx, *y, *yn, *f1;
    cudaGetSymbolAddress((void**)&xn,    g_xn);
    cudaGetSymbolAddress((void**)&q,     g_q);
    cudaGetSymbolAddress((void**)&k,     g_k);
    cudaGetSymbolAddress((void**)&v,     g_v);
    cudaGetSymbolAddress((void**)&z,     g_z);
    cudaGetSymbolAddress((void**)&dbuf,  g_dbuf);
    cudaGetSymbolAddress((void**)&gamma, g_gamma);
    cudaGetSymbolAddress((void**)&ctx,   g_ctx);
    cudaGetSymbolAddress((void**)&y,     g_y);
    cudaGetSymbolAddress((void**)&yn,    g_yn);
    cudaGetSymbolAddress((void**)&f1,    g_f1);

    dim3 gQKV(D / 128, M / 128);        // (8, 32)
    dim3 gQKVZ(D / 128, M / 128, 4);    // (8, 32, 4) batched
    dim3 gR(RD / 128, M / 128);         // (2, 32)
    dim3 gF1(FD / 128, M / 128);        // (32, 32)

    // 1) pre-norm + batched QKVZ projections (one launch, full chip packing)
    rmsnorm_kernel<<<M, 256>>>(x, wn1, xn);
    sgemm_qkvz_kernel<<<gQKVZ, 256>>>(xn, Wq, Wk, Wv, Wz, bq, bk, bv, bz, q, k, v, z);

    // 2) decay gamma
    sgemm_kernel<1, 0><<<gR, 256>>>(z, Wd, bd, nullptr, dbuf, RD, D);
    sgemm_kernel<2, 0><<<gQKV, 256>>>(dbuf, Wu, bu, nullptr, gamma, D, RD);

    // 3) associative scan + k scaling
    scan_chunk_kernel<<<dim3(D / 128, NCH, B), 128>>>();
    scan_pref_kernel<<<dim3(D / 128, B), 128>>>();
    kscale_kernel<<<2048, 256>>>();

    // 4) sequential gated recurrence (fused poll + h-fetch barrier)
    flag_reset_kernel<<<16, 256>>>();
    recur_kernel<<<128, 256>>>(Wg, bg);

    // 5) causal attention
    scores_kernel<<<dim3(S / 64, S / 64, BH), 256>>>(q, k);
    softmax_kernel<<<BH * S, 256>>>();
    pv_kernel<<<dim3(S / 64, BH), 256>>>(v);   // ctx = P@V + h fused

    // 6) residual + output projection
    sgemm_kernel<0, 1><<<gQKV, 256>>>(ctx, Wo, bo, x, y, D, D);

    // 7) FFN
    rmsnorm_kernel<<<M, 256>>>(y, wn2, yn);
    sgemm_kernel<3, 0><<<gF1, 256>>>(yn, Wf1, bf1, nullptr, f1, FD, D);
    sgemm_kernel<0, 1><<<gQKV, 256>>>(f1, Wf2, bf2, y, out, D, FD);
}